// round 2
// baseline (speedup 1.0000x reference)
#include <cuda_runtime.h>
#include <cstdint>

// ============================================================================
// KroneckerLinear: y[t] = U^T * X_t * V, per-token 128x128x128 GEMM pair.
// mma.sync.m16n8k8.tf32 (works on base compute_103 target; tcgen05 does NOT
// survive this harness's PTX target). Persistent CTAs, 1 CTA/SM, 8 warps.
// ============================================================================

static constexpr int LDP = 132;                 // padded row stride (floats)
static constexpr int MAT_U32 = 128 * LDP;       // 16896 u32 per matrix image
static constexpr int SMEM_BYTES = 3 * MAT_U32 * 4;  // 202752 B

// Pre-transposed tf32 images: g_Ut[n1*LDP+m1] = tf32(U[m1][n1]),
//                             g_Vt[n2*LDP+m2] = tf32(V[m2][n2])
__device__ uint32_t g_Ut[MAT_U32];
__device__ uint32_t g_Vt[MAT_U32];

__device__ __forceinline__ uint32_t f2tf(float f) {
    uint32_t r;
    asm("cvt.rna.tf32.f32 %0, %1;" : "=r"(r) : "f"(f));
    return r;
}

__device__ __forceinline__ void mma8(float c[4], const uint32_t a[4],
                                     uint32_t b0, uint32_t b1) {
    asm volatile(
        "mma.sync.aligned.m16n8k8.row.col.f32.tf32.tf32.f32 "
        "{%0,%1,%2,%3}, {%4,%5,%6,%7}, {%8,%9}, {%0,%1,%2,%3};"
        : "+f"(c[0]), "+f"(c[1]), "+f"(c[2]), "+f"(c[3])
        : "r"(a[0]), "r"(a[1]), "r"(a[2]), "r"(a[3]), "r"(b0), "r"(b1));
}

// ---------------------------------------------------------------------------
// Setup: build transposed tf32 images (padded) once.
// ---------------------------------------------------------------------------
__global__ void kron_setup(const float* __restrict__ U, const float* __restrict__ V) {
    uint32_t e = blockIdx.x * blockDim.x + threadIdx.x;
    if (e >= 16384u) return;
    uint32_t n = e >> 7;     // output row (transposed)
    uint32_t m = e & 127u;   // contraction index
    g_Ut[n * LDP + m] = f2tf(U[m * 128u + n]);
    g_Vt[n * LDP + m] = f2tf(V[m * 128u + n]);
}

// ---------------------------------------------------------------------------
// One 128x128x128 GEMM: C[i][j] = sum_k A[i][k] * B[j][k]
// A, B: padded [128][LDP] tf32 images in smem. Warp tile 32x64.
// c[2][8][4] accumulators (zeroed by caller).
// ---------------------------------------------------------------------------
__device__ __forceinline__ void gemm128(const uint32_t* __restrict__ A,
                                        const uint32_t* __restrict__ B,
                                        float c[2][8][4],
                                        int m0, int n0, int g, int tg) {
    #pragma unroll
    for (int k0 = 0; k0 < 128; k0 += 8) {
        uint32_t a[2][4];
        #pragma unroll
        for (int mt = 0; mt < 2; mt++) {
            int r = m0 + mt * 16 + g;
            a[mt][0] = A[r * LDP + k0 + tg];
            a[mt][1] = A[(r + 8) * LDP + k0 + tg];
            a[mt][2] = A[r * LDP + k0 + tg + 4];
            a[mt][3] = A[(r + 8) * LDP + k0 + tg + 4];
        }
        #pragma unroll
        for (int nt = 0; nt < 8; nt++) {
            int nrow = n0 + nt * 8 + g;
            uint32_t b0 = B[nrow * LDP + k0 + tg];
            uint32_t b1 = B[nrow * LDP + k0 + tg + 4];
            mma8(c[0][nt], a[0], b0, b1);
            mma8(c[1][nt], a[1], b0, b1);
        }
    }
}

// ---------------------------------------------------------------------------
// Main: persistent CTA (1 per SM). Smem: [Ut | Vt | X/Tt].
// ---------------------------------------------------------------------------
__global__ void __launch_bounds__(256, 1)
kron_main(const float* __restrict__ x, float* __restrict__ out, int ntok) {
    extern __shared__ uint32_t smem[];
    uint32_t* Uts = smem;
    uint32_t* Vts = smem + MAT_U32;
    uint32_t* Xs  = smem + 2 * MAT_U32;   // holds X, then reused for T^T

    const int tid = threadIdx.x;
    const int wid = tid >> 5;
    const int lid = tid & 31;
    const int g   = lid >> 2;   // groupID
    const int tg  = lid & 3;    // threadID_in_group
    const int m0  = (wid & 3) * 32;
    const int n0  = (wid >> 2) * 64;

    // Stage U^T, V^T images once (16B vector copies).
    {
        const uint4* us = reinterpret_cast<const uint4*>(g_Ut);
        const uint4* vs = reinterpret_cast<const uint4*>(g_Vt);
        uint4* ud = reinterpret_cast<uint4*>(Uts);
        uint4* vd = reinterpret_cast<uint4*>(Vts);
        #pragma unroll 4
        for (int i = tid; i < MAT_U32 / 4; i += 256) {
            ud[i] = us[i];
            vd[i] = vs[i];
        }
    }
    __syncthreads();

    for (int t = blockIdx.x; t < ntok; t += gridDim.x) {
        // ---- stage X (fp32 -> tf32, padded) ----
        {
            const float4* xt = reinterpret_cast<const float4*>(x + (size_t)t * 16384u);
            #pragma unroll 4
            for (int i = tid; i < 4096; i += 256) {
                float4 f = xt[i];
                int m = i >> 5, kq = (i & 31) * 4;
                uint4 p;
                p.x = f2tf(f.x); p.y = f2tf(f.y); p.z = f2tf(f.z); p.w = f2tf(f.w);
                *reinterpret_cast<uint4*>(&Xs[m * LDP + kq]) = p;
            }
        }
        __syncthreads();

        // ---- GEMM1: T[m1][n2] = sum_m2 X[m1][m2] * V[m2][n2] ----
        float c[2][8][4];
        #pragma unroll
        for (int i = 0; i < 2; i++)
            #pragma unroll
            for (int j = 0; j < 8; j++)
                #pragma unroll
                for (int q = 0; q < 4; q++) c[i][j][q] = 0.f;

        gemm128(Xs, Vts, c, m0, n0, g, tg);
        __syncthreads();   // all warps done reading Xs

        // ---- write T^T into Xs: Tt[n2][m1] = T[m1][n2] (as tf32) ----
        #pragma unroll
        for (int mt = 0; mt < 2; mt++) {
            int r0 = m0 + mt * 16 + g;
            #pragma unroll
            for (int nt = 0; nt < 8; nt++) {
                int col = n0 + nt * 8 + 2 * tg;
                Xs[col * LDP + r0]           = f2tf(c[mt][nt][0]);
                Xs[(col + 1) * LDP + r0]     = f2tf(c[mt][nt][1]);
                Xs[col * LDP + r0 + 8]       = f2tf(c[mt][nt][2]);
                Xs[(col + 1) * LDP + r0 + 8] = f2tf(c[mt][nt][3]);
            }
        }
        __syncthreads();

        // ---- GEMM2: Y[n1][n2] = sum_m1 Ut[n1][m1] * Tt[n2][m1] ----
        #pragma unroll
        for (int i = 0; i < 2; i++)
            #pragma unroll
            for (int j = 0; j < 8; j++)
                #pragma unroll
                for (int q = 0; q < 4; q++) c[i][j][q] = 0.f;

        gemm128(Uts, Xs, c, m0, n0, g, tg);

        // ---- store Y straight from accumulators ----
        {
            float* o = out + (size_t)t * 16384u;
            #pragma unroll
            for (int mt = 0; mt < 2; mt++) {
                int n1 = m0 + mt * 16 + g;
                #pragma unroll
                for (int nt = 0; nt < 8; nt++) {
                    int n2 = n0 + nt * 8 + 2 * tg;
                    float2 lo = make_float2(c[mt][nt][0], c[mt][nt][1]);
                    float2 hi = make_float2(c[mt][nt][2], c[mt][nt][3]);
                    *reinterpret_cast<float2*>(o + n1 * 128 + n2)       = lo;
                    *reinterpret_cast<float2*>(o + (n1 + 8) * 128 + n2) = hi;
                }
            }
        }
        __syncthreads();   // protect Xs before next token's staging
    }
}

// ---------------------------------------------------------------------------

extern "C" void kernel_launch(void* const* d_in, const int* in_sizes, int n_in,
                              void* d_out, int out_size) {
    (void)n_in; (void)out_size;
    const float* x = (const float*)d_in[0];
    const float* U = (const float*)d_in[1];
    const float* V = (const float*)d_in[2];
    float* out = (float*)d_out;
    const int ntok = in_sizes[0] / 16384;

    static int sm_count = 0;
    if (sm_count == 0) {
        cudaDeviceGetAttribute(&sm_count, cudaDevAttrMultiProcessorCount, 0);
        if (sm_count <= 0) sm_count = 148;
        cudaFuncSetAttribute(kron_main, cudaFuncAttributeMaxDynamicSharedMemorySize,
                             SMEM_BYTES);
    }
    int grid = sm_count < ntok ? sm_count : ntok;

    kron_setup<<<64, 256>>>(U, V);
    kron_main<<<grid, 256, SMEM_BYTES>>>(x, out, ntok);
}

// round 3
// speedup vs baseline: 1.9270x; 1.9270x over previous
#include <cuda_runtime.h>
#include <cuda_fp16.h>
#include <cstdint>

// ============================================================================
// KroneckerLinear: y[t] = U^T * X_t * V  (per-token 128x128x128 GEMM pair)
// fp16 mma.sync.m16n8k16 (fp32 accum) + ldmatrix + cp.async token pipeline.
// fp16 mantissa == tf32 mantissa (10 bits) -> same accuracy, 2x tensor rate.
// Persistent CTAs, 1 CTA/SM, 16 warps, warp tile 32x32.
// ============================================================================

static constexpr int TOK = 16384;

// smem layout (bytes)
static constexpr int OFF_X32 = 0;         // raw fp32 token (cp.async dst), 64KB
static constexpr int OFF_X16 = 65536;     // X as swizzled fp16 [m1][m2], 32KB
static constexpr int OFF_VT  = 98304;     // V^T image [n2][m2], 32KB
static constexpr int OFF_UT  = 131072;    // U^T image [n1][m1], 32KB
static constexpr int OFF_TT  = 163840;    // T^T image [n2][m1], 32KB
static constexpr int SMEM_BYTES = 196608; // 192KB -> 1 CTA/SM

// Pre-built swizzled fp16 images of U^T / V^T.
__device__ __half g_Ut[16384];
__device__ __half g_Vt[16384];

// swizzled half-index of element (row r, k) in a [128 x 128] fp16 tile:
// byte = r*256 + ((k*2) ^ ((r&7)<<4))  ->  half idx = r*128 + (k ^ ((r&7)<<3))
__host__ __device__ __forceinline__ int himg(int r, int k) {
    return r * 128 + (k ^ ((r & 7) << 3));
}

__device__ __forceinline__ uint32_t smem_u32(const void* p) {
    uint32_t a;
    asm("{ .reg .u64 t; cvta.to.shared.u64 t, %1; cvt.u32.u64 %0, t; }"
        : "=r"(a) : "l"(p));
    return a;
}

#define LDMX4(r, addr)                                                        \
    asm volatile("ldmatrix.sync.aligned.m8n8.x4.shared.b16 {%0,%1,%2,%3}, [%4];" \
        : "=r"((r)[0]), "=r"((r)[1]), "=r"((r)[2]), "=r"((r)[3]) : "r"(addr))

#define MMA16816(c, a, b0, b1)                                                \
    asm volatile(                                                             \
        "mma.sync.aligned.m16n8k16.row.col.f32.f16.f16.f32 "                  \
        "{%0,%1,%2,%3},{%4,%5,%6,%7},{%8,%9},{%0,%1,%2,%3};"                  \
        : "+f"((c)[0]), "+f"((c)[1]), "+f"((c)[2]), "+f"((c)[3])              \
        : "r"((a)[0]), "r"((a)[1]), "r"((a)[2]), "r"((a)[3]), "r"(b0), "r"(b1))

#define CP_ASYNC16(saddr, gptr)                                               \
    asm volatile("cp.async.cg.shared.global [%0], [%1], 16;"                  \
        :: "r"(saddr), "l"(gptr))

// ---------------------------------------------------------------------------
__global__ void kron_setup(const float* __restrict__ U, const float* __restrict__ V) {
    int e = blockIdx.x * blockDim.x + threadIdx.x;
    if (e >= 16384) return;
    int n = e >> 7;    // output row of transposed image
    int m = e & 127;   // contraction index
    g_Ut[himg(n, m)] = __float2half_rn(U[m * 128 + n]);
    g_Vt[himg(n, m)] = __float2half_rn(V[m * 128 + n]);
}

// ---------------------------------------------------------------------------
// One 128x128x128 GEMM, warp tile 32x32: C[i][j] = sum_k A[i][k]*B[j][k].
// A, B are swizzled fp16 [128][128] images (smem u32 base addresses).
// ---------------------------------------------------------------------------
__device__ __forceinline__ void gemm32x32(uint32_t Ab, uint32_t Bb,
                                          float c[2][4][4],
                                          int m0, int n0,
                                          uint32_t lrow, uint32_t lsw, uint32_t lk) {
    #pragma unroll
    for (int k0 = 0; k0 < 128; k0 += 16) {
        uint32_t koff = ((uint32_t)(2 * k0) + lk) ^ lsw;
        uint32_t a[2][4], b[2][4];
        #pragma unroll
        for (int mt = 0; mt < 2; mt++) {
            uint32_t ad = Ab + (uint32_t)(m0 + mt * 16 + lrow) * 256u + koff;
            LDMX4(a[mt], ad);
        }
        #pragma unroll
        for (int nb = 0; nb < 2; nb++) {
            uint32_t bd = Bb + (uint32_t)(n0 + nb * 16 + lrow) * 256u + koff;
            LDMX4(b[nb], bd);
        }
        #pragma unroll
        for (int mt = 0; mt < 2; mt++) {
            MMA16816(c[mt][0], a[mt], b[0][0], b[0][2]);
            MMA16816(c[mt][1], a[mt], b[0][1], b[0][3]);
            MMA16816(c[mt][2], a[mt], b[1][0], b[1][2]);
            MMA16816(c[mt][3], a[mt], b[1][1], b[1][3]);
        }
    }
}

// ---------------------------------------------------------------------------
__global__ void __launch_bounds__(512, 1)
kron_main(const float* __restrict__ x, float* __restrict__ out, int ntok) {
    extern __shared__ char smem[];
    const uint32_t sb = smem_u32(smem);
    const int tid = threadIdx.x;
    const int wid = tid >> 5;
    const int lid = tid & 31;
    const int g   = lid >> 2;
    const int tg  = lid & 3;
    const int m0  = (wid & 3) * 32;
    const int n0  = (wid >> 2) * 32;
    // ldmatrix per-lane addressing constants
    const uint32_t lrow = (uint32_t)(lid & 15);
    const uint32_t lsw  = (uint32_t)((lid & 7) << 4);
    const uint32_t lk   = (uint32_t)(lid & 16);

    // Stage U^T / V^T fp16 images once (straight 16B copies, layout-identical).
    {
        const uint4* us = reinterpret_cast<const uint4*>(g_Ut);
        const uint4* vs = reinterpret_cast<const uint4*>(g_Vt);
        uint4* ud = reinterpret_cast<uint4*>(smem + OFF_UT);
        uint4* vd = reinterpret_cast<uint4*>(smem + OFF_VT);
        #pragma unroll
        for (int i = tid; i < 2048; i += 512) { ud[i] = us[i]; vd[i] = vs[i]; }
    }

    // Prefetch first token (raw fp32) into X32.
    int t = blockIdx.x;
    if (t < ntok) {
        const char* src = reinterpret_cast<const char*>(x + (size_t)t * TOK);
        #pragma unroll
        for (int it = 0; it < 8; it++) {
            int i = tid + it * 512;
            CP_ASYNC16(sb + OFF_X32 + (uint32_t)i * 16u, src + (size_t)i * 16);
        }
    }
    asm volatile("cp.async.commit_group;" ::: "memory");

    for (; t < ntok; t += gridDim.x) {
        asm volatile("cp.async.wait_group 0;" ::: "memory");
        __syncthreads();

        // ---- convert X32 (fp32) -> X16 (swizzled fp16) ----
        {
            const float4* xs = reinterpret_cast<const float4*>(smem + OFF_X32);
            __half* xh = reinterpret_cast<__half*>(smem + OFF_X16);
            #pragma unroll
            for (int it = 0; it < 8; it++) {
                int i = tid + it * 512;
                float4 f = xs[i];
                int m = i >> 5, k4 = (i & 31) * 4;
                __half2 lo = __floats2half2_rn(f.x, f.y);
                __half2 hi = __floats2half2_rn(f.z, f.w);
                int hidx = m * 128 + (k4 ^ ((m & 7) << 3));
                uint2 p;
                p.x = reinterpret_cast<uint32_t&>(lo);
                p.y = reinterpret_cast<uint32_t&>(hi);
                *reinterpret_cast<uint2*>(xh + hidx) = p;
            }
        }
        __syncthreads();

        // ---- issue cp.async for next token (hidden behind both GEMMs) ----
        {
            int tn = t + (int)gridDim.x;
            if (tn < ntok) {
                const char* src = reinterpret_cast<const char*>(x + (size_t)tn * TOK);
                #pragma unroll
                for (int it = 0; it < 8; it++) {
                    int i = tid + it * 512;
                    CP_ASYNC16(sb + OFF_X32 + (uint32_t)i * 16u, src + (size_t)i * 16);
                }
            }
            asm volatile("cp.async.commit_group;" ::: "memory");
        }

        // ---- GEMM1: T[m1][n2] = sum_m2 X[m1][m2] * V[m2][n2] ----
        float c[2][4][4];
        #pragma unroll
        for (int i = 0; i < 2; i++)
            #pragma unroll
            for (int j = 0; j < 4; j++)
                #pragma unroll
                for (int q = 0; q < 4; q++) c[i][j][q] = 0.f;

        gemm32x32(sb + OFF_X16, sb + OFF_VT, c, m0, n0, lrow, lsw, lk);

        // ---- write T^T (fp16, swizzled) into TT ----
        {
            __half* tt = reinterpret_cast<__half*>(smem + OFF_TT);
            #pragma unroll
            for (int mt = 0; mt < 2; mt++)
                #pragma unroll
                for (int nt = 0; nt < 4; nt++)
                    #pragma unroll
                    for (int q = 0; q < 4; q++) {
                        int m1 = m0 + mt * 16 + g + ((q & 2) ? 8 : 0);
                        int n2 = n0 + nt * 8 + 2 * tg + (q & 1);
                        tt[n2 * 128 + (m1 ^ ((n2 & 7) << 3))] =
                            __float2half_rn(c[mt][nt][q]);
                    }
        }
        __syncthreads();

        // ---- GEMM2: Y[n1][n2] = sum_m1 Ut[n1][m1] * Tt[n2][m1] ----
        #pragma unroll
        for (int i = 0; i < 2; i++)
            #pragma unroll
            for (int j = 0; j < 4; j++)
                #pragma unroll
                for (int q = 0; q < 4; q++) c[i][j][q] = 0.f;

        gemm32x32(sb + OFF_UT, sb + OFF_TT, c, m0, n0, lrow, lsw, lk);

        // ---- epilogue: Y -> gmem straight from accumulators ----
        {
            float* o = out + (size_t)t * TOK;
            #pragma unroll
            for (int mt = 0; mt < 2; mt++) {
                int n1 = m0 + mt * 16 + g;
                #pragma unroll
                for (int nt = 0; nt < 4; nt++) {
                    int n2 = n0 + nt * 8 + 2 * tg;
                    *reinterpret_cast<float2*>(o + n1 * 128 + n2) =
                        make_float2(c[mt][nt][0], c[mt][nt][1]);
                    *reinterpret_cast<float2*>(o + (n1 + 8) * 128 + n2) =
                        make_float2(c[mt][nt][2], c[mt][nt][3]);
                }
            }
        }
        __syncthreads();  // TT/X16 reuse protection for next iteration
    }
}

// ---------------------------------------------------------------------------
extern "C" void kernel_launch(void* const* d_in, const int* in_sizes, int n_in,
                              void* d_out, int out_size) {
    (void)n_in; (void)out_size;
    const float* x = (const float*)d_in[0];
    const float* U = (const float*)d_in[1];
    const float* V = (const float*)d_in[2];
    float* out = (float*)d_out;
    const int ntok = in_sizes[0] / TOK;

    static int sm_count = 0;
    if (sm_count == 0) {
        cudaDeviceGetAttribute(&sm_count, cudaDevAttrMultiProcessorCount, 0);
        if (sm_count <= 0) sm_count = 148;
        cudaFuncSetAttribute(kron_main, cudaFuncAttributeMaxDynamicSharedMemorySize,
                             SMEM_BYTES);
    }
    int grid = sm_count < ntok ? sm_count : ntok;

    kron_setup<<<64, 256>>>(U, V);
    kron_main<<<grid, 512, SMEM_BYTES>>>(x, out, ntok);
}

// round 4
// speedup vs baseline: 2.0253x; 1.0510x over previous
#include <cuda_runtime.h>
#include <cuda_fp16.h>
#include <cstdint>

// ============================================================================
// KroneckerLinear: y[t] = U^T * X_t * V  (per-token 128x128x128 GEMM pair)
// fp16 m16n8k16 mma + ldmatrix + cp.async pipeline. Persistent CTAs, 16 warps.
// R4: T stored in natural [m1][n2] layout (conflict-free STS.32), transposed
// on load via ldmatrix.x4.trans -> kills the scalar-scatter L1 hotspot.
// ============================================================================

static constexpr int TOK = 16384;

// smem layout (bytes)
static constexpr int OFF_X32 = 0;         // raw fp32 token (cp.async dst), 64KB
static constexpr int OFF_X16 = 65536;     // X as swizzled fp16 [m1][m2], 32KB
static constexpr int OFF_VT  = 98304;     // V^T image [n2][m2], 32KB
static constexpr int OFF_UT  = 131072;    // U^T image [n1][m1], 32KB
static constexpr int OFF_T   = 163840;    // T image [m1][n2] (natural), 32KB
static constexpr int SMEM_BYTES = 196608; // 192KB -> 1 CTA/SM

__device__ __half g_Ut[16384];
__device__ __half g_Vt[16384];

// swizzled half-index of (row r, col k) in a [128x128] fp16 tile (256B rows):
// byte = r*256 + ((k*2) ^ ((r&7)<<4))
__host__ __device__ __forceinline__ int himg(int r, int k) {
    return r * 128 + (k ^ ((r & 7) << 3));
}

__device__ __forceinline__ uint32_t smem_u32(const void* p) {
    uint32_t a;
    asm("{ .reg .u64 t; cvta.to.shared.u64 t, %1; cvt.u32.u64 %0, t; }"
        : "=r"(a) : "l"(p));
    return a;
}

#define LDMX4(r, addr)                                                        \
    asm volatile("ldmatrix.sync.aligned.m8n8.x4.shared.b16 {%0,%1,%2,%3}, [%4];" \
        : "=r"((r)[0]), "=r"((r)[1]), "=r"((r)[2]), "=r"((r)[3]) : "r"(addr))

#define LDMX4T(r, addr)                                                       \
    asm volatile("ldmatrix.sync.aligned.m8n8.x4.trans.shared.b16 {%0,%1,%2,%3}, [%4];" \
        : "=r"((r)[0]), "=r"((r)[1]), "=r"((r)[2]), "=r"((r)[3]) : "r"(addr))

#define MMA16816(c, a, b0, b1)                                                \
    asm volatile(                                                             \
        "mma.sync.aligned.m16n8k16.row.col.f32.f16.f16.f32 "                  \
        "{%0,%1,%2,%3},{%4,%5,%6,%7},{%8,%9},{%0,%1,%2,%3};"                  \
        : "+f"((c)[0]), "+f"((c)[1]), "+f"((c)[2]), "+f"((c)[3])              \
        : "r"((a)[0]), "r"((a)[1]), "r"((a)[2]), "r"((a)[3]), "r"(b0), "r"(b1))

#define CP_ASYNC16(saddr, gptr)                                               \
    asm volatile("cp.async.cg.shared.global [%0], [%1], 16;"                  \
        :: "r"(saddr), "l"(gptr))

// ---------------------------------------------------------------------------
__global__ void kron_setup(const float* __restrict__ U, const float* __restrict__ V) {
    int e = blockIdx.x * blockDim.x + threadIdx.x;
    if (e >= 16384) return;
    int n = e >> 7;
    int m = e & 127;
    g_Ut[himg(n, m)] = __float2half_rn(U[m * 128 + n]);
    g_Vt[himg(n, m)] = __float2half_rn(V[m * 128 + n]);
}

// ---------------------------------------------------------------------------
// GEMM variant 1: A [i][k] swizzled image, B [j][k] swizzled image (non-trans).
// C[i][j] += sum_k A[i][k]*B[j][k].  Warp tile 32x32.
// ---------------------------------------------------------------------------
__device__ __forceinline__ void gemm_nn(uint32_t Ab, uint32_t Bb,
                                        float c[2][4][4],
                                        int m0, int n0,
                                        uint32_t lrow, uint32_t lsw, uint32_t lk) {
    #pragma unroll
    for (int k0 = 0; k0 < 128; k0 += 16) {
        uint32_t koff = ((uint32_t)(2 * k0) + lk) ^ lsw;
        uint32_t a[2][4], b[2][4];
        #pragma unroll
        for (int mt = 0; mt < 2; mt++)
            LDMX4(a[mt], Ab + (uint32_t)(m0 + mt * 16 + lrow) * 256u + koff);
        #pragma unroll
        for (int nb = 0; nb < 2; nb++)
            LDMX4(b[nb], Bb + (uint32_t)(n0 + nb * 16 + lrow) * 256u + koff);
        #pragma unroll
        for (int mt = 0; mt < 2; mt++) {
            MMA16816(c[mt][0], a[mt], b[0][0], b[0][2]);
            MMA16816(c[mt][1], a[mt], b[0][1], b[0][3]);
            MMA16816(c[mt][2], a[mt], b[1][0], b[1][2]);
            MMA16816(c[mt][3], a[mt], b[1][1], b[1][3]);
        }
    }
}

// ---------------------------------------------------------------------------
// GEMM variant 2: A [i][k] swizzled (non-trans), B stored as [k][j] swizzled
// image, loaded with ldmatrix.trans. C[i][j] += sum_k A[i][k]*B[k][j].
// Trans tile addressing: rows = k (addr &B[k0+lrow][ncol]), per-lane ncol
// offset +8 for lanes 16-31 (lk>>1).
// ---------------------------------------------------------------------------
__device__ __forceinline__ void gemm_nt(uint32_t Ab, uint32_t Bb,
                                        float c[2][4][4],
                                        int m0, int n0,
                                        uint32_t lrow, uint32_t lsw, uint32_t lk) {
    const uint32_t ncol_lane = (uint32_t)n0 + (lk >> 1);  // +8 cols for hi lanes
    #pragma unroll
    for (int k0 = 0; k0 < 128; k0 += 16) {
        uint32_t koff = ((uint32_t)(2 * k0) + lk) ^ lsw;
        uint32_t a[2][4], b[2][4];
        #pragma unroll
        for (int mt = 0; mt < 2; mt++)
            LDMX4(a[mt], Ab + (uint32_t)(m0 + mt * 16 + lrow) * 256u + koff);
        #pragma unroll
        for (int nb = 0; nb < 2; nb++) {
            uint32_t ncol = ncol_lane + (uint32_t)(nb * 16);
            uint32_t addr = Bb + (uint32_t)(k0 + lrow) * 256u + ((ncol * 2u) ^ lsw);
            LDMX4T(b[nb], addr);
        }
        // trans pairing: (r0,r1) = n-block lo, (r2,r3) = n-block hi
        #pragma unroll
        for (int mt = 0; mt < 2; mt++) {
            MMA16816(c[mt][0], a[mt], b[0][0], b[0][1]);
            MMA16816(c[mt][1], a[mt], b[0][2], b[0][3]);
            MMA16816(c[mt][2], a[mt], b[1][0], b[1][1]);
            MMA16816(c[mt][3], a[mt], b[1][2], b[1][3]);
        }
    }
}

// ---------------------------------------------------------------------------
__global__ void __launch_bounds__(512, 1)
kron_main(const float* __restrict__ x, float* __restrict__ out, int ntok) {
    extern __shared__ char smem[];
    const uint32_t sb = smem_u32(smem);
    const int tid = threadIdx.x;
    const int wid = tid >> 5;
    const int lid = tid & 31;
    const int g   = lid >> 2;
    const int tg  = lid & 3;
    const int m0  = (wid & 3) * 32;
    const int n0  = (wid >> 2) * 32;
    const uint32_t lrow = (uint32_t)(lid & 15);
    const uint32_t lsw  = (uint32_t)((lid & 7) << 4);
    const uint32_t lk   = (uint32_t)(lid & 16);

    // Stage U^T / V^T fp16 images once.
    {
        const uint4* us = reinterpret_cast<const uint4*>(g_Ut);
        const uint4* vs = reinterpret_cast<const uint4*>(g_Vt);
        uint4* ud = reinterpret_cast<uint4*>(smem + OFF_UT);
        uint4* vd = reinterpret_cast<uint4*>(smem + OFF_VT);
        #pragma unroll
        for (int i = tid; i < 2048; i += 512) { ud[i] = us[i]; vd[i] = vs[i]; }
    }

    // Prefetch first token.
    int t = blockIdx.x;
    if (t < ntok) {
        const char* src = reinterpret_cast<const char*>(x + (size_t)t * TOK);
        #pragma unroll
        for (int it = 0; it < 8; it++) {
            int i = tid + it * 512;
            CP_ASYNC16(sb + OFF_X32 + (uint32_t)i * 16u, src + (size_t)i * 16);
        }
    }
    asm volatile("cp.async.commit_group;" ::: "memory");

    for (; t < ntok; t += gridDim.x) {
        asm volatile("cp.async.wait_group 0;" ::: "memory");
        __syncthreads();

        // ---- convert X32 (fp32) -> X16 (swizzled fp16 [m1][m2]) ----
        {
            const float4* xs = reinterpret_cast<const float4*>(smem + OFF_X32);
            __half* xh = reinterpret_cast<__half*>(smem + OFF_X16);
            #pragma unroll
            for (int it = 0; it < 8; it++) {
                int i = tid + it * 512;
                float4 f = xs[i];
                int m = i >> 5, k4 = (i & 31) * 4;
                __half2 lo = __floats2half2_rn(f.x, f.y);
                __half2 hi = __floats2half2_rn(f.z, f.w);
                uint2 p;
                p.x = reinterpret_cast<uint32_t&>(lo);
                p.y = reinterpret_cast<uint32_t&>(hi);
                *reinterpret_cast<uint2*>(xh + m * 128 + (k4 ^ ((m & 7) << 3))) = p;
            }
        }
        __syncthreads();

        // ---- issue cp.async for next token (hidden behind both GEMMs) ----
        {
            int tn = t + (int)gridDim.x;
            if (tn < ntok) {
                const char* src = reinterpret_cast<const char*>(x + (size_t)tn * TOK);
                #pragma unroll
                for (int it = 0; it < 8; it++) {
                    int i = tid + it * 512;
                    CP_ASYNC16(sb + OFF_X32 + (uint32_t)i * 16u, src + (size_t)i * 16);
                }
            }
            asm volatile("cp.async.commit_group;" ::: "memory");
        }

        // ---- GEMM1: T[m1][n2] = sum_m2 X[m1][m2] * V[m2][n2] ----
        float c[2][4][4];
        #pragma unroll
        for (int i = 0; i < 2; i++)
            #pragma unroll
            for (int j = 0; j < 4; j++)
                #pragma unroll
                for (int q = 0; q < 4; q++) c[i][j][q] = 0.f;

        gemm_nn(sb + OFF_X16, sb + OFF_VT, c, m0, n0, lrow, lsw, lk);

        // ---- store T in natural [m1][n2] layout (conflict-free STS.32) ----
        {
            __half* th = reinterpret_cast<__half*>(smem + OFF_T);
            #pragma unroll
            for (int mt = 0; mt < 2; mt++) {
                #pragma unroll
                for (int nt = 0; nt < 4; nt++) {
                    int m1 = m0 + mt * 16 + g;
                    int n2 = n0 + nt * 8 + 2 * tg;
                    __half2 lo = __floats2half2_rn(c[mt][nt][0], c[mt][nt][1]);
                    __half2 hi = __floats2half2_rn(c[mt][nt][2], c[mt][nt][3]);
                    *reinterpret_cast<__half2*>(
                        th + m1 * 128 + (n2 ^ ((m1 & 7) << 3))) = lo;
                    *reinterpret_cast<__half2*>(
                        th + (m1 + 8) * 128 + (n2 ^ (((m1 + 8) & 7) << 3))) = hi;
                }
            }
        }
        __syncthreads();

        // ---- GEMM2: Y[n1][n2] = sum_m1 Ut[n1][m1] * T[m1][n2] (trans-B) ----
        #pragma unroll
        for (int i = 0; i < 2; i++)
            #pragma unroll
            for (int j = 0; j < 4; j++)
                #pragma unroll
                for (int q = 0; q < 4; q++) c[i][j][q] = 0.f;

        gemm_nt(sb + OFF_UT, sb + OFF_T, c, m0, n0, lrow, lsw, lk);

        // ---- epilogue: Y -> gmem straight from accumulators ----
        {
            float* o = out + (size_t)t * TOK;
            #pragma unroll
            for (int mt = 0; mt < 2; mt++) {
                int n1 = m0 + mt * 16 + g;
                #pragma unroll
                for (int nt = 0; nt < 4; nt++) {
                    int n2 = n0 + nt * 8 + 2 * tg;
                    *reinterpret_cast<float2*>(o + n1 * 128 + n2) =
                        make_float2(c[mt][nt][0], c[mt][nt][1]);
                    *reinterpret_cast<float2*>(o + (n1 + 8) * 128 + n2) =
                        make_float2(c[mt][nt][2], c[mt][nt][3]);
                }
            }
        }
        __syncthreads();  // X16/T reuse protection for next iteration
    }
}

// ---------------------------------------------------------------------------
extern "C" void kernel_launch(void* const* d_in, const int* in_sizes, int n_in,
                              void* d_out, int out_size) {
    (void)n_in; (void)out_size;
    const float* x = (const float*)d_in[0];
    const float* U = (const float*)d_in[1];
    const float* V = (const float*)d_in[2];
    float* out = (float*)d_out;
    const int ntok = in_sizes[0] / TOK;

    static int sm_count = 0;
    if (sm_count == 0) {
        cudaDeviceGetAttribute(&sm_count, cudaDevAttrMultiProcessorCount, 0);
        if (sm_count <= 0) sm_count = 148;
        cudaFuncSetAttribute(kron_main, cudaFuncAttributeMaxDynamicSharedMemorySize,
                             SMEM_BYTES);
    }
    int grid = sm_count < ntok ? sm_count : ntok;

    kron_setup<<<64, 256>>>(U, V);
    kron_main<<<grid, 512, SMEM_BYTES>>>(x, out, ntok);
}